// round 3
// baseline (speedup 1.0000x reference)
#include <cuda_runtime.h>

// Window attention, fully fused: one CTA per window (2048 CTAs, 384 threads).
// fp32 SIMT, register-tiled GEMMs, online-softmax attention (no spills),
// mask + rel-pos-bias staged in SMEM (kills uncoalesced gathers).

#define NTOK 64
#define DIM  192
#define NH   6
#define HD   32
#define SXS  196              // padded row stride (floats)
#define BUF  (NTOK * SXS)     // floats per 64x192 buffer
#define WSF  (8 * 192)        // weight tile: 8 k-rows x 192 cols
#define MSKS 65               // mask row stride (conflict-free, scalar access)
#define MSKF (64 * MSKS)
#define RPBF (225 * NH)       // 15*15 x 6 rel-pos table

__device__ __forceinline__ float getc(float4 v, int u) {
    return u == 0 ? v.x : u == 1 ? v.y : u == 2 ? v.z : v.w;
}
__device__ __forceinline__ float ex2(float x) {
    float y; asm("ex2.approx.ftz.f32 %0, %1;" : "=f"(y) : "f"(x)); return y;
}

__global__ __launch_bounds__(384, 1)
void win_attn_kernel(const float* __restrict__ x,
                     const float* __restrict__ mask,
                     const float* __restrict__ w_qkv,
                     const float* __restrict__ b_qkv,
                     const float* __restrict__ rpbt,
                     const float* __restrict__ w_proj,
                     const float* __restrict__ b_proj,
                     float* __restrict__ out)
{
    extern __shared__ float sm[];
    float* sx    = sm;                    // 64x192 input; reused for attn output
    float* sq    = sm + BUF;
    float* sk    = sm + 2 * BUF;
    float* sv    = sm + 3 * BUF;
    float* ws    = sm + 4 * BUF;          // 8x192 weight tile
    float* smask = ws + WSF;              // 64x65
    float* srpbt = smask + MSKF;          // 225x6

    const int tid = threadIdx.x;
    const int b   = blockIdx.x;
    const int tx  = tid % 24;             // 24 col-groups of 8
    const int ty  = tid / 24;             // 16 row-groups of 4

    const float SCALE = 0.17677669529663689f;   // 32^-0.5
    const float LOG2E = 1.4426950408889634f;

    // ---------------- Phase 1: stage x, mask, rpbt into SMEM ----------------
    {
        const float* xg = x + (size_t)b * (NTOK * DIM);
        #pragma unroll
        for (int i = 0; i < 8; ++i) {
            int f  = tid + i * 384;                 // 3072 float4
            int r  = f / 48;
            int c4 = f % 48;
            *(float4*)&sx[r * SXS + c4 * 4] = *(const float4*)&xg[r * DIM + c4 * 4];
        }
        const int wwin = b & 63;
        const float* mg = mask + (size_t)wwin * (NTOK * NTOK);
        for (int f = tid; f < 1024; f += 384) {     // 64x64 floats as float4
            int r = f >> 4, c = (f & 15) * 4;
            float4 v = *(const float4*)&mg[r * 64 + c];
            smask[r * MSKS + c + 0] = v.x;
            smask[r * MSKS + c + 1] = v.y;
            smask[r * MSKS + c + 2] = v.z;
            smask[r * MSKS + c + 3] = v.w;
        }
        for (int f = tid; f < RPBF; f += 384) srpbt[f] = rpbt[f];
    }
    // ordered by the first __syncthreads inside the tile loop below

    // ---------------- Phase 2: qkv = x @ w_qkv + b_qkv ----------------
    #pragma unroll 1
    for (int m = 0; m < 3; ++m) {
        float acc[4][8];
        #pragma unroll
        for (int i = 0; i < 4; ++i)
            #pragma unroll
            for (int c = 0; c < 8; ++c) acc[i][c] = 0.f;

        #pragma unroll 1
        for (int k0 = 0; k0 < DIM; k0 += 8) {
            __syncthreads();
            {   // 8 k-rows x 192 cols = 384 float4, one per thread
                int kk = tid / 48, c4 = tid % 48;
                *(float4*)&ws[kk * 192 + c4 * 4] =
                    *(const float4*)&w_qkv[(k0 + kk) * 576 + m * 192 + c4 * 4];
            }
            __syncthreads();

            #pragma unroll
            for (int kq = 0; kq < 2; ++kq) {
                float4 a4[4];
                #pragma unroll
                for (int i = 0; i < 4; ++i)
                    a4[i] = *(const float4*)&sx[(ty * 4 + i) * SXS + k0 + kq * 4];
                #pragma unroll
                for (int u = 0; u < 4; ++u) {
                    int kk = kq * 4 + u;
                    float4 b4[2];
                    #pragma unroll
                    for (int c = 0; c < 2; ++c)
                        b4[c] = *(const float4*)&ws[kk * 192 + tx * 8 + c * 4];
                    #pragma unroll
                    for (int i = 0; i < 4; ++i) {
                        float av = getc(a4[i], u);
                        #pragma unroll
                        for (int c = 0; c < 8; ++c)
                            acc[i][c] = fmaf(av, getc(b4[c >> 2], c & 3), acc[i][c]);
                    }
                }
            }
        }

        float* dst = (m == 0) ? sq : (m == 1) ? sk : sv;
        float scl  = (m == 0) ? SCALE : 1.0f;
        #pragma unroll
        for (int i = 0; i < 4; ++i)
            #pragma unroll
            for (int c = 0; c < 8; ++c) {
                int col = tx * 8 + c;
                dst[(ty * 4 + i) * SXS + col] =
                    (acc[i][c] + __ldg(&b_qkv[m * 192 + col])) * scl;
            }
    }
    __syncthreads();

    // ------- Phase 3: attention, one (head,row) per thread, online softmax ---
    {
        const int head = tid >> 6;        // 384 threads = 6 heads x 64 rows
        const int row  = tid & 63;
        const int rh   = row >> 3, rw = row & 7;

        float4 q4[8];
        {
            const float4* qr = (const float4*)(sq + row * SXS + head * HD);
            #pragma unroll
            for (int u = 0; u < 8; ++u) q4[u] = qr[u];
        }

        float mx = -1e30f, s = 0.f;
        float4 o[8];
        #pragma unroll
        for (int u = 0; u < 8; ++u) o[u] = make_float4(0.f, 0.f, 0.f, 0.f);

        #pragma unroll 1
        for (int j0 = 0; j0 < NTOK; j0 += 16) {
            float att[16];
            #pragma unroll
            for (int jj = 0; jj < 16; ++jj) {
                int j = j0 + jj;
                const float4* kr = (const float4*)(sk + j * SXS + head * HD);
                float d = 0.f;
                #pragma unroll
                for (int u = 0; u < 8; ++u) {
                    float4 kv = kr[u];
                    d = fmaf(q4[u].x, kv.x, d);
                    d = fmaf(q4[u].y, kv.y, d);
                    d = fmaf(q4[u].z, kv.z, d);
                    d = fmaf(q4[u].w, kv.w, d);
                }
                int idx = (rh - (j >> 3) + 7) * 15 + (rw - (j & 7) + 7);
                att[jj] = d + srpbt[idx * NH + head] + smask[row * MSKS + j];
            }

            float cm = att[0];
            #pragma unroll
            for (int jj = 1; jj < 16; ++jj) cm = fmaxf(cm, att[jj]);
            float nm = fmaxf(mx, cm);
            float rs = ex2((mx - nm) * LOG2E);
            s *= rs;
            #pragma unroll
            for (int u = 0; u < 8; ++u) {
                o[u].x *= rs; o[u].y *= rs; o[u].z *= rs; o[u].w *= rs;
            }
            #pragma unroll
            for (int jj = 0; jj < 16; ++jj) {
                float p = ex2((att[jj] - nm) * LOG2E);
                s += p;
                const float4* vr = (const float4*)(sv + (j0 + jj) * SXS + head * HD);
                #pragma unroll
                for (int u = 0; u < 8; ++u) {
                    float4 vv = vr[u];
                    o[u].x = fmaf(p, vv.x, o[u].x);
                    o[u].y = fmaf(p, vv.y, o[u].y);
                    o[u].z = fmaf(p, vv.z, o[u].z);
                    o[u].w = fmaf(p, vv.w, o[u].w);
                }
            }
            mx = nm;
        }

        const float inv = 1.f / s;
        float4* dst = (float4*)(sx + row * SXS + head * HD);   // reuse sx
        #pragma unroll
        for (int u = 0; u < 8; ++u)
            dst[u] = make_float4(o[u].x * inv, o[u].y * inv,
                                 o[u].z * inv, o[u].w * inv);
    }
    __syncthreads();

    // ---------------- Phase 4: out = x_att @ w_proj + b_proj ----------------
    {
        float acc[4][8];
        #pragma unroll
        for (int i = 0; i < 4; ++i)
            #pragma unroll
            for (int c = 0; c < 8; ++c) acc[i][c] = 0.f;

        #pragma unroll 1
        for (int k0 = 0; k0 < DIM; k0 += 8) {
            __syncthreads();
            {
                int kk = tid / 48, c4 = tid % 48;
                *(float4*)&ws[kk * 192 + c4 * 4] =
                    *(const float4*)&w_proj[(k0 + kk) * 192 + c4 * 4];
            }
            __syncthreads();

            #pragma unroll
            for (int kq = 0; kq < 2; ++kq) {
                float4 a4[4];
                #pragma unroll
                for (int i = 0; i < 4; ++i)
                    a4[i] = *(const float4*)&sx[(ty * 4 + i) * SXS + k0 + kq * 4];
                #pragma unroll
                for (int u = 0; u < 4; ++u) {
                    int kk = kq * 4 + u;
                    float4 b4[2];
                    #pragma unroll
                    for (int c = 0; c < 2; ++c)
                        b4[c] = *(const float4*)&ws[kk * 192 + tx * 8 + c * 4];
                    #pragma unroll
                    for (int i = 0; i < 4; ++i) {
                        float av = getc(a4[i], u);
                        #pragma unroll
                        for (int c = 0; c < 8; ++c)
                            acc[i][c] = fmaf(av, getc(b4[c >> 2], c & 3), acc[i][c]);
                    }
                }
            }
        }

        float* og = out + (size_t)b * (NTOK * DIM);
        #pragma unroll
        for (int i = 0; i < 4; ++i) {
            #pragma unroll
            for (int c4 = 0; c4 < 2; ++c4) {
                int col = tx * 8 + c4 * 4;
                float4 v;
                v.x = acc[i][c4 * 4 + 0] + __ldg(&b_proj[col + 0]);
                v.y = acc[i][c4 * 4 + 1] + __ldg(&b_proj[col + 1]);
                v.z = acc[i][c4 * 4 + 2] + __ldg(&b_proj[col + 2]);
                v.w = acc[i][c4 * 4 + 3] + __ldg(&b_proj[col + 3]);
                *(float4*)&og[(ty * 4 + i) * DIM + col] = v;
            }
        }
    }
}

extern "C" void kernel_launch(void* const* d_in, const int* in_sizes, int n_in,
                              void* d_out, int out_size)
{
    const float* x      = (const float*)d_in[0];
    const float* mask   = (const float*)d_in[1];
    const float* w_qkv  = (const float*)d_in[2];
    const float* b_qkv  = (const float*)d_in[3];
    const float* rpbt   = (const float*)d_in[4];
    const float* w_proj = (const float*)d_in[5];
    const float* b_proj = (const float*)d_in[6];
    float* out = (float*)d_out;

    const int smem_bytes = (4 * BUF + WSF + MSKF + RPBF) * (int)sizeof(float);
    cudaFuncSetAttribute(win_attn_kernel,
                         cudaFuncAttributeMaxDynamicSharedMemorySize, smem_bytes);

    win_attn_kernel<<<2048, 384, smem_bytes>>>(x, mask, w_qkv, b_qkv,
                                               rpbt, w_proj, b_proj, out);
}

// round 5
// speedup vs baseline: 2.2177x; 2.2177x over previous
#include <cuda_runtime.h>
#include <cuda_bf16.h>
#include <cstdint>

#define NTOK 64
#define DIM  192
#define NH   6
#define HD   32
#define NWIN 2048
#define MTOT (NWIN * NTOK)     // 131072
#define QKVN 576

// ------------------------- device scratch (static) -------------------------
__device__ float g_qkv[MTOT * QKVN];            // qkv output, fp32
__device__ float g_att[MTOT * DIM];             // attention output, fp32
__device__ __nv_bfloat16 g_wqh[QKVN * DIM];     // w_qkv^T hi (scaled q cols)
__device__ __nv_bfloat16 g_wql[QKVN * DIM];     // w_qkv^T lo
__device__ __nv_bfloat16 g_wph[DIM * DIM];      // w_proj^T hi
__device__ __nv_bfloat16 g_wpl[DIM * DIM];      // w_proj^T lo
__device__ float g_bq[QKVN];                    // qkv bias (scaled q part)

__device__ __forceinline__ uint32_t smem_u32(const void* p) {
    uint32_t a;
    asm("{ .reg .u64 t; cvta.to.shared.u64 t, %1; cvt.u32.u64 %0, t; }"
        : "=r"(a) : "l"(p));
    return a;
}
__device__ __forceinline__ uint32_t pkbf(__nv_bfloat16 a, __nv_bfloat16 b) {
    return (uint32_t)__bfloat16_as_ushort(a)
         | ((uint32_t)__bfloat16_as_ushort(b) << 16);
}

#define LDSM4(r, addr)                                                      \
    asm volatile("ldmatrix.sync.aligned.m8n8.x4.shared.b16 "                \
                 "{%0,%1,%2,%3}, [%4];"                                     \
                 : "=r"((r)[0]), "=r"((r)[1]), "=r"((r)[2]), "=r"((r)[3])   \
                 : "r"(addr))

#define MMA16816(c, a, b0, b1)                                              \
    asm volatile("mma.sync.aligned.m16n8k16.row.col.f32.bf16.bf16.f32 "     \
                 "{%0,%1,%2,%3}, {%4,%5,%6,%7}, {%8,%9}, {%0,%1,%2,%3};"    \
                 : "+f"((c)[0]), "+f"((c)[1]), "+f"((c)[2]), "+f"((c)[3])   \
                 : "r"((a)[0]), "r"((a)[1]), "r"((a)[2]), "r"((a)[3]),      \
                   "r"(b0), "r"(b1))

// ------------------------- prep: split + transpose weights -------------------------
__global__ void prep_kernel(const float* __restrict__ wqkv,
                            const float* __restrict__ bqkv,
                            const float* __restrict__ wproj)
{
    const float SCALE = 0.17677669529663689f;
    int i = blockIdx.x * 256 + threadIdx.x;
    if (i < QKVN * DIM) {
        int n = i % QKVN, k = i / QKVN;               // coalesced read
        float v = wqkv[k * QKVN + n];
        if (n < DIM) v *= SCALE;                       // fold q scale
        __nv_bfloat16 h = __float2bfloat16(v);
        g_wqh[n * DIM + k] = h;
        g_wql[n * DIM + k] = __float2bfloat16(v - __bfloat162float(h));
    }
    if (i < DIM * DIM) {
        int n = i % DIM, k = i / DIM;
        float v = wproj[k * DIM + n];
        __nv_bfloat16 h = __float2bfloat16(v);
        g_wph[n * DIM + k] = h;
        g_wpl[n * DIM + k] = __float2bfloat16(v - __bfloat162float(h));
    }
    if (i < QKVN) g_bq[i] = (i < DIM) ? bqkv[i] * SCALE : bqkv[i];
}

// --------- mma.sync bf16-split GEMM: C[M,ntot] = A[M,192] @ B^T + bias ----------
// B pre-transposed+split: [N][192] bf16 hi/lo. CTA tile 128x64, 8 warps (4x2),
// warp tile 32x32. C = Ah*Bh + Ah*Bl + Al*Bh (error-compensated bf16).
#define MT   128
#define KD   192
#define ASTR 200              // bf16 elements per A row (padded)
#define BSTR 200
#define CSTR 68               // fp32 elements per C row (padded)
#define OFF_AH 0
#define OFF_AL (MT * ASTR * 2)                 // 51200
#define OFF_B  (2 * MT * ASTR * 2)             // 102400
#define OFF_BH OFF_B
#define OFF_BL (OFF_B + 64 * BSTR * 2)         // +25600
#define OFF_C  OFF_B                           // reused after compute
#define GSMEM  (OFF_B + 2 * 64 * BSTR * 2)     // 153600

__global__ __launch_bounds__(256, 1)
void gemm_mma(const float* __restrict__ A,
              const __nv_bfloat16* __restrict__ Bh,
              const __nv_bfloat16* __restrict__ Bl,
              const float* __restrict__ bias,
              float* __restrict__ C,
              int ldc, int ntot)
{
    extern __shared__ char smem[];
    __nv_bfloat16* sAh = (__nv_bfloat16*)(smem + OFF_AH);
    __nv_bfloat16* sAl = (__nv_bfloat16*)(smem + OFF_AL);
    float*         sC  = (float*)(smem + OFF_C);
    const uint32_t sb  = smem_u32(smem);

    const int tid  = threadIdx.x;
    const int wid  = tid >> 5;
    const int lane = tid & 31;
    const int wm   = wid >> 1;        // 0..3
    const int wn   = wid & 1;         // 0..1

    // ---- stage A (128x192 fp32 -> bf16 hi/lo in SMEM) ----
    {
        const float* ag = A + (size_t)blockIdx.x * MT * KD;
        #pragma unroll
        for (int q = 0; q < 24; ++q) {
            int f  = tid + q * 256;            // 6144 float4
            int r  = f / 48, c4 = (f % 48) * 4;
            float4 v = *(const float4*)&ag[(size_t)r * KD + c4];
            __nv_bfloat16 h0 = __float2bfloat16(v.x);
            __nv_bfloat16 h1 = __float2bfloat16(v.y);
            __nv_bfloat16 h2 = __float2bfloat16(v.z);
            __nv_bfloat16 h3 = __float2bfloat16(v.w);
            uint2 hp, lp;
            hp.x = pkbf(h0, h1); hp.y = pkbf(h2, h3);
            lp.x = pkbf(__float2bfloat16(v.x - __bfloat162float(h0)),
                        __float2bfloat16(v.y - __bfloat162float(h1)));
            lp.y = pkbf(__float2bfloat16(v.z - __bfloat162float(h2)),
                        __float2bfloat16(v.w - __bfloat162float(h3)));
            *(uint2*)&sAh[r * ASTR + c4] = hp;
            *(uint2*)&sAl[r * ASTR + c4] = lp;
        }
    }

    // ---- precompute ldmatrix lane element-offsets (bytes) ----
    const int asub = lane >> 3, ar = lane & 7;
    uint32_t aeo[2], beo[2];
    #pragma unroll
    for (int t = 0; t < 2; ++t) {
        int row = wm * 32 + t * 16 + ar + (asub & 1) * 8;
        int col = (asub >> 1) * 8;
        aeo[t] = (uint32_t)(row * ASTR + col) * 2u;
    }
    #pragma unroll
    for (int p = 0; p < 2; ++p) {
        int row = wn * 32 + p * 16 + ar + (asub >> 1) * 8;
        int col = (asub & 1) * 8;
        beo[p] = (uint32_t)(row * BSTR + col) * 2u;
    }

    const int nchunks = ntot / 64;
    #pragma unroll 1
    for (int nc = 0; nc < nchunks; ++nc) {
        __syncthreads();   // orders A staging (first iter) / prior sC reads

        // ---- stage B hi/lo (64x192 bf16 each) ----
        #pragma unroll
        for (int s2 = 0; s2 < 2; ++s2) {
            const __nv_bfloat16* src = (s2 ? Bl : Bh) + (size_t)(nc * 64) * KD;
            __nv_bfloat16* dst = (__nv_bfloat16*)(smem + (s2 ? OFF_BL : OFF_BH));
            #pragma unroll
            for (int q = 0; q < 6; ++q) {
                int g = tid + q * 256;                 // 1536 granules of 16B
                int row = g / 24, gg = g % 24;
                *(uint4*)&dst[row * BSTR + gg * 8] =
                    *(const uint4*)&src[(size_t)row * KD + gg * 8];
            }
        }
        __syncthreads();

        // ---- compute: 3 split passes x 12 k16 steps ----
        float c[2][4][4];
        #pragma unroll
        for (int t = 0; t < 2; ++t)
            #pragma unroll
            for (int f = 0; f < 4; ++f)
                #pragma unroll
                for (int j = 0; j < 4; ++j) c[t][f][j] = 0.f;

        #pragma unroll 1
        for (int s = 0; s < 3; ++s) {
            uint32_t ab = sb + (s == 2 ? OFF_AL : OFF_AH);
            uint32_t bb = sb + (s == 1 ? OFF_BL : OFF_BH);
            #pragma unroll
            for (int k16 = 0; k16 < 12; ++k16) {
                uint32_t ko = (uint32_t)k16 * 32u;     // 16 el * 2B
                uint32_t a[2][4], bf[2][4];
                LDSM4(a[0], ab + aeo[0] + ko);
                LDSM4(a[1], ab + aeo[1] + ko);
                LDSM4(bf[0], bb + beo[0] + ko);
                LDSM4(bf[1], bb + beo[1] + ko);
                #pragma unroll
                for (int t = 0; t < 2; ++t) {
                    MMA16816(c[t][0], a[t], bf[0][0], bf[0][1]);
                    MMA16816(c[t][1], a[t], bf[0][2], bf[0][3]);
                    MMA16816(c[t][2], a[t], bf[1][0], bf[1][1]);
                    MMA16816(c[t][3], a[t], bf[1][2], bf[1][3]);
                }
            }
        }
        __syncthreads();   // all ldmatrix reads of sB done before sC overwrite

        // ---- epilogue: frags -> sC -> coalesced global + bias ----
        #pragma unroll
        for (int t = 0; t < 2; ++t) {
            int r0 = wm * 32 + t * 16 + (lane >> 2);
            #pragma unroll
            for (int f = 0; f < 4; ++f) {
                int cc = wn * 32 + f * 8 + (lane & 3) * 2;
                sC[r0 * CSTR + cc]           = c[t][f][0];
                sC[r0 * CSTR + cc + 1]       = c[t][f][1];
                sC[(r0 + 8) * CSTR + cc]     = c[t][f][2];
                sC[(r0 + 8) * CSTR + cc + 1] = c[t][f][3];
            }
        }
        __syncthreads();

        const int n0 = nc * 64;
        float* crow = C + (size_t)blockIdx.x * MT * ldc + n0;
        #pragma unroll
        for (int q = 0; q < 8; ++q) {
            int f = tid + q * 256;             // 2048 float4
            int r = f >> 4, c4 = (f & 15) * 4;
            float4 v = *(float4*)&sC[r * CSTR + c4];
            v.x += __ldg(&bias[n0 + c4 + 0]);
            v.y += __ldg(&bias[n0 + c4 + 1]);
            v.z += __ldg(&bias[n0 + c4 + 2]);
            v.w += __ldg(&bias[n0 + c4 + 3]);
            *(float4*)&crow[(size_t)r * ldc + c4] = v;
        }
    }
}

// ------------------------- SIMT fp32 attention -------------------------
#define SXS 196
#define ABUF (NTOK * SXS)
#define MSKS 65

__global__ __launch_bounds__(384, 1)
void attn_kernel(const float* __restrict__ mask,
                 const float* __restrict__ rpbt)
{
    extern __shared__ float sm[];
    float* sq    = sm;
    float* sk    = sm + ABUF;
    float* sv    = sm + 2 * ABUF;
    float* smask = sm + 3 * ABUF;         // 64 x 65
    float* srp   = smask + 64 * MSKS;     // 225 x 6

    const int tid = threadIdx.x;
    const int b   = blockIdx.x;
    const float LOG2E = 1.4426950408889634f;

    {
        const float* qg = g_qkv + (size_t)b * (NTOK * QKVN);
        for (int f = tid; f < NTOK * 48; f += 384) {
            int r = f / 48, c4 = (f % 48) * 4;
            *(float4*)&sq[r * SXS + c4] = *(const float4*)(qg + (size_t)r * QKVN + c4);
            *(float4*)&sk[r * SXS + c4] = *(const float4*)(qg + (size_t)r * QKVN + 192 + c4);
            *(float4*)&sv[r * SXS + c4] = *(const float4*)(qg + (size_t)r * QKVN + 384 + c4);
        }
        const float* mg = mask + (size_t)(b & 63) * (NTOK * NTOK);
        for (int f = tid; f < 1024; f += 384) {
            int r = f >> 4, c = (f & 15) * 4;
            float4 v = *(const float4*)&mg[r * 64 + c];
            smask[r * MSKS + c + 0] = v.x; smask[r * MSKS + c + 1] = v.y;
            smask[r * MSKS + c + 2] = v.z; smask[r * MSKS + c + 3] = v.w;
        }
        for (int f = tid; f < 225 * NH; f += 384) srp[f] = rpbt[f];
    }
    __syncthreads();

    const int head = tid >> 6;            // 6 heads x 64 rows = 384 threads
    const int row  = tid & 63;
    const int rh = row >> 3, rw = row & 7;

    float4 q4[8];
    {
        const float4* qr = (const float4*)(sq + row * SXS + head * HD);
        #pragma unroll
        for (int u = 0; u < 8; ++u) q4[u] = qr[u];
    }

    float mx = -1e30f, ssum = 0.f;
    float4 o[8];
    #pragma unroll
    for (int u = 0; u < 8; ++u) o[u] = make_float4(0.f, 0.f, 0.f, 0.f);

    #pragma unroll 1
    for (int j0 = 0; j0 < NTOK; j0 += 32) {
        float att[32];
        #pragma unroll
        for (int jj = 0; jj < 32; ++jj) {
            int j = j0 + jj;
            const float4* kr = (const float4*)(sk + j * SXS + head * HD);
            float d = 0.f;
            #pragma unroll
            for (int u = 0; u < 8; ++u) {
                float4 kv = kr[u];
                d = fmaf(q4[u].x, kv.x, d); d = fmaf(q4[u].y, kv.y, d);
                d = fmaf(q4[u].z, kv.z, d); d = fmaf(q4[u].w, kv.w, d);
            }
            int idx = (rh - (j >> 3) + 7) * 15 + (rw - (j & 7) + 7);
            att[jj] = d + srp[idx * NH + head] + smask[row * MSKS + j];
        }
        float cm = att[0];
        #pragma unroll
        for (int jj = 1; jj < 32; ++jj) cm = fmaxf(cm, att[jj]);
        float nm = fmaxf(mx, cm);
        float rs = exp2f((mx - nm) * LOG2E);
        ssum *= rs;
        #pragma unroll
        for (int u = 0; u < 8; ++u) {
            o[u].x *= rs; o[u].y *= rs; o[u].z *= rs; o[u].w *= rs;
        }
        #pragma unroll
        for (int jj = 0; jj < 32; ++jj) {
            float p = exp2f((att[jj] - nm) * LOG2E);
            ssum += p;
            const float4* vr = (const float4*)(sv + (j0 + jj) * SXS + head * HD);
            #pragma unroll
            for (int u = 0; u < 8; ++u) {
                float4 vv = vr[u];
                o[u].x = fmaf(p, vv.x, o[u].x); o[u].y = fmaf(p, vv.y, o[u].y);
                o[u].z = fmaf(p, vv.z, o[u].z); o[u].w = fmaf(p, vv.w, o[u].w);
            }
        }
        mx = nm;
    }
    const float inv = 1.f / ssum;
    float* dst = g_att + ((size_t)b * NTOK + row) * DIM + head * HD;
    #pragma unroll
    for (int u = 0; u < 8; ++u)
        *(float4*)(dst + u * 4) = make_float4(o[u].x * inv, o[u].y * inv,
                                              o[u].z * inv, o[u].w * inv);
}

// ------------------------- launch -------------------------
extern "C" void kernel_launch(void* const* d_in, const int* in_sizes, int n_in,
                              void* d_out, int out_size)
{
    const float* x      = (const float*)d_in[0];
    const float* mask   = (const float*)d_in[1];
    const float* w_qkv  = (const float*)d_in[2];
    const float* b_qkv  = (const float*)d_in[3];
    const float* rpbt   = (const float*)d_in[4];
    const float* w_proj = (const float*)d_in[5];
    const float* b_proj = (const float*)d_in[6];
    float* out = (float*)d_out;

    void *p_qkv, *p_att, *p_wqh, *p_wql, *p_wph, *p_wpl, *p_bq;
    cudaGetSymbolAddress(&p_qkv, g_qkv);
    cudaGetSymbolAddress(&p_att, g_att);
    cudaGetSymbolAddress(&p_wqh, g_wqh);
    cudaGetSymbolAddress(&p_wql, g_wql);
    cudaGetSymbolAddress(&p_wph, g_wph);
    cudaGetSymbolAddress(&p_wpl, g_wpl);
    cudaGetSymbolAddress(&p_bq,  g_bq);

    cudaFuncSetAttribute(gemm_mma,
                         cudaFuncAttributeMaxDynamicSharedMemorySize, GSMEM);
    const int attn_smem = (3 * ABUF + 64 * MSKS + 225 * NH) * (int)sizeof(float);
    cudaFuncSetAttribute(attn_kernel,
                         cudaFuncAttributeMaxDynamicSharedMemorySize, attn_smem);

    prep_kernel<<<432, 256>>>(w_qkv, b_qkv, w_proj);

    gemm_mma<<<MTOT / MT, 256, GSMEM>>>(
        x, (const __nv_bfloat16*)p_wqh, (const __nv_bfloat16*)p_wql,
        (const float*)p_bq, (float*)p_qkv, QKVN, QKVN);

    attn_kernel<<<NWIN, 384, attn_smem>>>(mask, rpbt);

    gemm_mma<<<MTOT / MT, 256, GSMEM>>>(
        (const float*)p_att, (const __nv_bfloat16*)p_wph, (const __nv_bfloat16*)p_wpl,
        b_proj, out, DIM, DIM);
}

// round 7
// speedup vs baseline: 2.4141x; 1.0886x over previous
#include <cuda_runtime.h>
#include <cuda_bf16.h>
#include <cstdint>

#define NTOK 64
#define DIM  192
#define NH   6
#define HD   32
#define NWIN 2048
#define MTOT (NWIN * NTOK)     // 131072
#define QKVN 576

// ------------------------- device scratch (static) -------------------------
__device__ float g_qkv[MTOT * QKVN];            // qkv output, fp32
__device__ float g_att[MTOT * DIM];             // attention output, fp32
__device__ __nv_bfloat16 g_wqh[QKVN * DIM];     // w_qkv^T hi (scaled q cols)
__device__ __nv_bfloat16 g_wql[QKVN * DIM];     // w_qkv^T lo
__device__ __nv_bfloat16 g_wph[DIM * DIM];      // w_proj^T hi
__device__ __nv_bfloat16 g_wpl[DIM * DIM];      // w_proj^T lo
__device__ float g_bq[QKVN];                    // qkv bias (scaled q part)

__device__ __forceinline__ uint32_t smem_u32(const void* p) {
    uint32_t a;
    asm("{ .reg .u64 t; cvta.to.shared.u64 t, %1; cvt.u32.u64 %0, t; }"
        : "=r"(a) : "l"(p));
    return a;
}
__device__ __forceinline__ uint32_t pkbf(__nv_bfloat16 a, __nv_bfloat16 b) {
    return (uint32_t)__bfloat16_as_ushort(a)
         | ((uint32_t)__bfloat16_as_ushort(b) << 16);
}
__device__ __forceinline__ float ex2(float x) {
    float y; asm("ex2.approx.ftz.f32 %0, %1;" : "=f"(y) : "f"(x)); return y;
}

#define LDSM4(r, addr)                                                      \
    asm volatile("ldmatrix.sync.aligned.m8n8.x4.shared.b16 "                \
                 "{%0,%1,%2,%3}, [%4];"                                     \
                 : "=r"((r)[0]), "=r"((r)[1]), "=r"((r)[2]), "=r"((r)[3])   \
                 : "r"(addr))

#define MMA16816(c, a, b0, b1)                                              \
    asm volatile("mma.sync.aligned.m16n8k16.row.col.f32.bf16.bf16.f32 "     \
                 "{%0,%1,%2,%3}, {%4,%5,%6,%7}, {%8,%9}, {%0,%1,%2,%3};"    \
                 : "+f"((c)[0]), "+f"((c)[1]), "+f"((c)[2]), "+f"((c)[3])   \
                 : "r"((a)[0]), "r"((a)[1]), "r"((a)[2]), "r"((a)[3]),      \
                   "r"(b0), "r"(b1))

// ------------------------- prep: split + transpose weights -------------------------
__global__ void prep_kernel(const float* __restrict__ wqkv,
                            const float* __restrict__ bqkv,
                            const float* __restrict__ wproj)
{
    const float SCALE = 0.17677669529663689f;
    int i = blockIdx.x * 256 + threadIdx.x;
    if (i < QKVN * DIM) {
        int n = i % QKVN, k = i / QKVN;               // coalesced read
        float v = wqkv[k * QKVN + n];
        if (n < DIM) v *= SCALE;                       // fold q scale
        __nv_bfloat16 h = __float2bfloat16(v);
        g_wqh[n * DIM + k] = h;
        g_wql[n * DIM + k] = __float2bfloat16(v - __bfloat162float(h));
    }
    if (i < DIM * DIM) {
        int n = i % DIM, k = i / DIM;
        float v = wproj[k * DIM + n];
        __nv_bfloat16 h = __float2bfloat16(v);
        g_wph[n * DIM + k] = h;
        g_wpl[n * DIM + k] = __float2bfloat16(v - __bfloat162float(h));
    }
    if (i < QKVN) g_bq[i] = (i < DIM) ? bqkv[i] * SCALE : bqkv[i];
}

// --------- mma.sync bf16-split GEMM: C[M,ntot] = A[M,192] @ B^T + bias ----------
#define MT   128
#define KD   192
#define ASTR 200
#define BSTR 200
#define CSTR 68
#define OFF_AH 0
#define OFF_AL (MT * ASTR * 2)                 // 51200
#define OFF_B  (2 * MT * ASTR * 2)             // 102400
#define OFF_BH OFF_B
#define OFF_BL (OFF_B + 64 * BSTR * 2)         // +25600
#define OFF_C  OFF_B                           // reused after compute
#define GSMEM  (OFF_B + 2 * 64 * BSTR * 2)     // 153600

__global__ __launch_bounds__(256, 1)
void gemm_mma(const float* __restrict__ A,
              const __nv_bfloat16* __restrict__ Bh,
              const __nv_bfloat16* __restrict__ Bl,
              const float* __restrict__ bias,
              float* __restrict__ C,
              int ldc, int ntot)
{
    extern __shared__ char smem[];
    __nv_bfloat16* sAh = (__nv_bfloat16*)(smem + OFF_AH);
    __nv_bfloat16* sAl = (__nv_bfloat16*)(smem + OFF_AL);
    float*         sC  = (float*)(smem + OFF_C);
    const uint32_t sb  = smem_u32(smem);

    const int tid  = threadIdx.x;
    const int wid  = tid >> 5;
    const int lane = tid & 31;
    const int wm   = wid >> 1;
    const int wn   = wid & 1;

    {
        const float* ag = A + (size_t)blockIdx.x * MT * KD;
        #pragma unroll
        for (int q = 0; q < 24; ++q) {
            int f  = tid + q * 256;
            int r  = f / 48, c4 = (f % 48) * 4;
            float4 v = *(const float4*)&ag[(size_t)r * KD + c4];
            __nv_bfloat16 h0 = __float2bfloat16(v.x);
            __nv_bfloat16 h1 = __float2bfloat16(v.y);
            __nv_bfloat16 h2 = __float2bfloat16(v.z);
            __nv_bfloat16 h3 = __float2bfloat16(v.w);
            uint2 hp, lp;
            hp.x = pkbf(h0, h1); hp.y = pkbf(h2, h3);
            lp.x = pkbf(__float2bfloat16(v.x - __bfloat162float(h0)),
                        __float2bfloat16(v.y - __bfloat162float(h1)));
            lp.y = pkbf(__float2bfloat16(v.z - __bfloat162float(h2)),
                        __float2bfloat16(v.w - __bfloat162float(h3)));
            *(uint2*)&sAh[r * ASTR + c4] = hp;
            *(uint2*)&sAl[r * ASTR + c4] = lp;
        }
    }

    const int asub = lane >> 3, ar = lane & 7;
    uint32_t aeo[2], beo[2];
    #pragma unroll
    for (int t = 0; t < 2; ++t) {
        int row = wm * 32 + t * 16 + ar + (asub & 1) * 8;
        int col = (asub >> 1) * 8;
        aeo[t] = (uint32_t)(row * ASTR + col) * 2u;
    }
    #pragma unroll
    for (int p = 0; p < 2; ++p) {
        int row = wn * 32 + p * 16 + ar + (asub >> 1) * 8;
        int col = (asub & 1) * 8;
        beo[p] = (uint32_t)(row * BSTR + col) * 2u;
    }

    const int nchunks = ntot / 64;
    #pragma unroll 1
    for (int nc = 0; nc < nchunks; ++nc) {
        __syncthreads();

        #pragma unroll
        for (int s2 = 0; s2 < 2; ++s2) {
            const __nv_bfloat16* src = (s2 ? Bl : Bh) + (size_t)(nc * 64) * KD;
            __nv_bfloat16* dst = (__nv_bfloat16*)(smem + (s2 ? OFF_BL : OFF_BH));
            #pragma unroll
            for (int q = 0; q < 6; ++q) {
                int g = tid + q * 256;
                int row = g / 24, gg = g % 24;
                *(uint4*)&dst[row * BSTR + gg * 8] =
                    *(const uint4*)&src[(size_t)row * KD + gg * 8];
            }
        }
        __syncthreads();

        float c[2][4][4];
        #pragma unroll
        for (int t = 0; t < 2; ++t)
            #pragma unroll
            for (int f = 0; f < 4; ++f)
                #pragma unroll
                for (int j = 0; j < 4; ++j) c[t][f][j] = 0.f;

        #pragma unroll 1
        for (int s = 0; s < 3; ++s) {
            uint32_t ab = sb + (s == 2 ? OFF_AL : OFF_AH);
            uint32_t bb = sb + (s == 1 ? OFF_BL : OFF_BH);
            #pragma unroll
            for (int k16 = 0; k16 < 12; ++k16) {
                uint32_t ko = (uint32_t)k16 * 32u;
                uint32_t a[2][4], bf[2][4];
                LDSM4(a[0], ab + aeo[0] + ko);
                LDSM4(a[1], ab + aeo[1] + ko);
                LDSM4(bf[0], bb + beo[0] + ko);
                LDSM4(bf[1], bb + beo[1] + ko);
                #pragma unroll
                for (int t = 0; t < 2; ++t) {
                    MMA16816(c[t][0], a[t], bf[0][0], bf[0][1]);
                    MMA16816(c[t][1], a[t], bf[0][2], bf[0][3]);
                    MMA16816(c[t][2], a[t], bf[1][0], bf[1][1]);
                    MMA16816(c[t][3], a[t], bf[1][2], bf[1][3]);
                }
            }
        }
        __syncthreads();

        #pragma unroll
        for (int t = 0; t < 2; ++t) {
            int r0 = wm * 32 + t * 16 + (lane >> 2);
            #pragma unroll
            for (int f = 0; f < 4; ++f) {
                int cc = wn * 32 + f * 8 + (lane & 3) * 2;
                sC[r0 * CSTR + cc]           = c[t][f][0];
                sC[r0 * CSTR + cc + 1]       = c[t][f][1];
                sC[(r0 + 8) * CSTR + cc]     = c[t][f][2];
                sC[(r0 + 8) * CSTR + cc + 1] = c[t][f][3];
            }
        }
        __syncthreads();

        const int n0 = nc * 64;
        float* crow = C + (size_t)blockIdx.x * MT * ldc + n0;
        #pragma unroll
        for (int q = 0; q < 8; ++q) {
            int f = tid + q * 256;
            int r = f >> 4, c4 = (f & 15) * 4;
            float4 v = *(float4*)&sC[r * CSTR + c4];
            v.x += __ldg(&bias[n0 + c4 + 0]);
            v.y += __ldg(&bias[n0 + c4 + 1]);
            v.z += __ldg(&bias[n0 + c4 + 2]);
            v.w += __ldg(&bias[n0 + c4 + 3]);
            *(float4*)&crow[(size_t)r * ldc + c4] = v;
        }
    }
}

// -------- attention: one CTA per (window, head), 64 threads, occ ~6/SM --------
#define MSKS 65
// smem floats: sk 64*32, sv 64*32, smask 64*65, srp 225
#define ATT_SK   0
#define ATT_SV   (64 * 32)
#define ATT_MSK  (2 * 64 * 32)
#define ATT_RP   (ATT_MSK + 64 * MSKS)
#define ATT_SMEMF (ATT_RP + 232)

__global__ __launch_bounds__(64, 6)
void attn_kernel(const float* __restrict__ mask,
                 const float* __restrict__ rpbt)
{
    extern __shared__ float sm[];
    float* sk    = sm + ATT_SK;
    float* sv    = sm + ATT_SV;
    float* smask = sm + ATT_MSK;
    float* srp   = sm + ATT_RP;

    const int tid  = threadIdx.x;
    const int win  = blockIdx.x;
    const int head = blockIdx.y;
    const float LOG2E = 1.4426950408889634f;

    const float* qg = g_qkv + (size_t)win * (NTOK * QKVN) + head * HD;

    // ---- stage k, v (this head only), mask, rpbt column ----
    #pragma unroll
    for (int q = 0; q < 8; ++q) {
        int f = tid + q * 64;              // 512 float4
        int r = f >> 3, c4 = (f & 7) * 4;
        const float* base = qg + (size_t)r * QKVN + c4;
        *(float4*)&sk[r * HD + c4] = *(const float4*)(base + 192);
        *(float4*)&sv[r * HD + c4] = *(const float4*)(base + 384);
    }
    {
        const float* mg = mask + (size_t)(win & 63) * (NTOK * NTOK);
        #pragma unroll
        for (int q = 0; q < 16; ++q) {
            int f = tid + q * 64;          // 1024 float4
            int r = f >> 4, c = (f & 15) * 4;
            float4 v = *(const float4*)&mg[r * 64 + c];
            smask[r * MSKS + c + 0] = v.x; smask[r * MSKS + c + 1] = v.y;
            smask[r * MSKS + c + 2] = v.z; smask[r * MSKS + c + 3] = v.w;
        }
        #pragma unroll
        for (int q = 0; q < 4; ++q) {
            int f = tid + q * 64;
            if (f < 225) srp[f] = __ldg(&rpbt[f * NH + head]);
        }
    }

    // ---- q row straight to registers (global, coalesced 128B/thread) ----
    const int row = tid;
    const int rh = row >> 3, rw = row & 7;
    float4 q4[8];
    {
        const float4* qr = (const float4*)(qg + (size_t)row * QKVN);
        #pragma unroll
        for (int u = 0; u < 8; ++u) q4[u] = qr[u];
    }
    __syncthreads();

    float mx = -1e30f, ssum = 0.f;
    float4 o[8];
    #pragma unroll
    for (int u = 0; u < 8; ++u) o[u] = make_float4(0.f, 0.f, 0.f, 0.f);

    #pragma unroll 1
    for (int j0 = 0; j0 < NTOK; j0 += 32) {
        float att[32];
        #pragma unroll
        for (int jj = 0; jj < 32; ++jj) {
            int j = j0 + jj;
            const float4* kr = (const float4*)(sk + j * HD);
            float d = 0.f;
            #pragma unroll
            for (int u = 0; u < 8; ++u) {
                float4 kv = kr[u];
                d = fmaf(q4[u].x, kv.x, d); d = fmaf(q4[u].y, kv.y, d);
                d = fmaf(q4[u].z, kv.z, d); d = fmaf(q4[u].w, kv.w, d);
            }
            int idx = (rh - (j >> 3) + 7) * 15 + (rw - (j & 7) + 7);
            att[jj] = d + srp[idx] + smask[row * MSKS + j];
        }
        float cm = att[0];
        #pragma unroll
        for (int jj = 1; jj < 32; ++jj) cm = fmaxf(cm, att[jj]);
        float nm = fmaxf(mx, cm);
        float rs = ex2((mx - nm) * LOG2E);
        ssum *= rs;
        #pragma unroll
        for (int u = 0; u < 8; ++u) {
            o[u].x *= rs; o[u].y *= rs; o[u].z *= rs; o[u].w *= rs;
        }
        #pragma unroll
        for (int jj = 0; jj < 32; ++jj) {
            float p = ex2((att[jj] - nm) * LOG2E);
            ssum += p;
            const float4* vr = (const float4*)(sv + (j0 + jj) * HD);
            #pragma unroll
            for (int u = 0; u < 8; ++u) {
                float4 vv = vr[u];
                o[u].x = fmaf(p, vv.x, o[u].x); o[u].y = fmaf(p, vv.y, o[u].y);
                o[u].z = fmaf(p, vv.z, o[u].z); o[u].w = fmaf(p, vv.w, o[u].w);
            }
        }
        mx = nm;
    }
    const float inv = 1.f / ssum;
    float* dst = g_att + ((size_t)win * NTOK + row) * DIM + head * HD;
    #pragma unroll
    for (int u = 0; u < 8; ++u)
        *(float4*)(dst + u * 4) = make_float4(o[u].x * inv, o[u].y * inv,
                                              o[u].z * inv, o[u].w * inv);
}

// ------------------------- launch -------------------------
extern "C" void kernel_launch(void* const* d_in, const int* in_sizes, int n_in,
                              void* d_out, int out_size)
{
    const float* x      = (const float*)d_in[0];
    const float* mask   = (const float*)d_in[1];
    const float* w_qkv  = (const float*)d_in[2];
    const float* b_qkv  = (const float*)d_in[3];
    const float* rpbt   = (const float*)d_in[4];
    const float* w_proj = (const float*)d_in[5];
    const float* b_proj = (const float*)d_in[6];
    float* out = (float*)d_out;

    void *p_qkv, *p_att, *p_wqh, *p_wql, *p_wph, *p_wpl, *p_bq;
    cudaGetSymbolAddress(&p_qkv, g_qkv);
    cudaGetSymbolAddress(&p_att, g_att);
    cudaGetSymbolAddress(&p_wqh, g_wqh);
    cudaGetSymbolAddress(&p_wql, g_wql);
    cudaGetSymbolAddress(&p_wph, g_wph);
    cudaGetSymbolAddress(&p_wpl, g_wpl);
    cudaGetSymbolAddress(&p_bq,  g_bq);

    cudaFuncSetAttribute(gemm_mma,
                         cudaFuncAttributeMaxDynamicSharedMemorySize, GSMEM);
    const int attn_smem = ATT_SMEMF * (int)sizeof(float);
    cudaFuncSetAttribute(attn_kernel,
                         cudaFuncAttributeMaxDynamicSharedMemorySize, attn_smem);

    prep_kernel<<<432, 256>>>(w_qkv, b_qkv, w_proj);

    gemm_mma<<<MTOT / MT, 256, GSMEM>>>(
        x, (const __nv_bfloat16*)p_wqh, (const __nv_bfloat16*)p_wql,
        (const float*)p_bq, (float*)p_qkv, QKVN, QKVN);

    dim3 agrid(NWIN, NH);
    attn_kernel<<<agrid, 64, attn_smem>>>(mask, rpbt);

    gemm_mma<<<MTOT / MT, 256, GSMEM>>>(
        (const float*)p_att, (const __nv_bfloat16*)p_wph, (const __nv_bfloat16*)p_wpl,
        b_proj, out, DIM, DIM);
}